// round 9
// baseline (speedup 1.0000x reference)
#include <cstdint>
#include <cuda_runtime.h>
#include <cuda_bf16.h>
#include <math_constants.h>

#define BB     2
#define TT     2048
#define DMODEL 1024
#define NHEADS 16
#define DHEAD  64
#define TOTALE 1024
#define E3     3072

__device__ float g_qkv[BB * TT * E3];
__device__ float g_att[BB * TT * TOTALE];

__device__ __forceinline__ float to_tf32(float x) {
    uint32_t r;
    asm("cvt.rna.tf32.f32 %0, %1;" : "=r"(r) : "f"(x));
    return __uint_as_float(r);
}

#define MMA_TF32(d, a, b)                                                     \
    asm volatile("mma.sync.aligned.m16n8k8.row.col.f32.tf32.tf32.f32 "        \
                 "{%0,%1,%2,%3}, {%4,%5,%6,%7}, {%8,%9}, {%0,%1,%2,%3};"      \
                 : "+f"(d[0]), "+f"(d[1]), "+f"(d[2]), "+f"(d[3])             \
                 : "r"(a[0]), "r"(a[1]), "r"(a[2]), "r"(a[3]),                \
                   "r"(b[0]), "r"(b[1]))

// ---------------------------------------------------------------------------
// tf32 GEMM: C[M,N] = A[M,K] @ B[N,K]^T, 128x128 tile, BK=32, 256 threads.
// Software-pipelined: register prefetch of tile i+2 overlaps MMA of tile i;
// double-buffered smem -> one barrier per K-step.
// ---------------------------------------------------------------------------
#define ABUF 4608                 // 128*36 floats
#define GSTAGE 9216               // A+B per stage
#define AS(b, r, c) sh[(b) * GSTAGE + (r) * 36 + (c)]
#define BS(b, r, c) sh[(b) * GSTAGE + ABUF + (r) * 36 + (c)]

__global__ void __launch_bounds__(256) gemm_tf32(const float* __restrict__ A,
                                                 const float* __restrict__ Bm,
                                                 float* __restrict__ C,
                                                 int M, int N, int K) {
    extern __shared__ float sh[];  // 2 stages * (As + Bs) = 73728 B

    const int tid = threadIdx.x;
    const int lane = tid & 31;
    const int w = tid >> 5;
    const int wm = (w >> 2) * 64;
    const int wn = (w & 3) * 32;
    const int bm = blockIdx.y * 128;
    const int bn = blockIdx.x * 128;
    const int lr = lane >> 2;
    const int lc = lane & 3;
    const int ldr = tid >> 3;
    const int ldc = (tid & 7) << 2;

    float acc[4][4][4];
#pragma unroll
    for (int i = 0; i < 4; ++i)
#pragma unroll
        for (int j = 0; j < 4; ++j)
#pragma unroll
            for (int r = 0; r < 4; ++r) acc[i][j][r] = 0.f;

    float4 ra[4], rb[4];

#define GEMM_LDG(k0)                                                          \
    {                                                                         \
        _Pragma("unroll") for (int i = 0; i < 4; ++i) {                       \
            int r = ldr + i * 32;                                             \
            ra[i] = *(const float4*)&A[(long)(bm + r) * K + (k0) + ldc];      \
            rb[i] = *(const float4*)&Bm[(long)(bn + r) * K + (k0) + ldc];     \
        }                                                                     \
    }
#define GEMM_STAGE(buf)                                                       \
    {                                                                         \
        _Pragma("unroll") for (int i = 0; i < 4; ++i) {                       \
            int r = ldr + i * 32;                                             \
            float4 va = ra[i];                                                \
            va.x = to_tf32(va.x); va.y = to_tf32(va.y);                       \
            va.z = to_tf32(va.z); va.w = to_tf32(va.w);                       \
            *(float4*)&AS(buf, r, ldc) = va;                                  \
            float4 vb = rb[i];                                                \
            vb.x = to_tf32(vb.x); vb.y = to_tf32(vb.y);                       \
            vb.z = to_tf32(vb.z); vb.w = to_tf32(vb.w);                       \
            *(float4*)&BS(buf, r, ldc) = vb;                                  \
        }                                                                     \
    }

    const int nk = K >> 5;  // 32-wide K steps
    GEMM_LDG(0);
    GEMM_STAGE(0);
    GEMM_LDG(32);
    __syncthreads();

    for (int it = 0; it < nk; ++it) {
        const int buf = it & 1;
        if (it + 1 < nk) {
            GEMM_STAGE(buf ^ 1);               // regs hold tile it+1
            if (it + 2 < nk) GEMM_LDG((it + 2) * 32);  // prefetch overlaps MMA
        }

#pragma unroll
        for (int ks = 0; ks < 4; ++ks) {
            const int kb = ks * 8;
            uint32_t a[4][4], b[4][2];
#pragma unroll
            for (int mt = 0; mt < 4; ++mt) {
                int rbw = wm + mt * 16 + lr;
                a[mt][0] = __float_as_uint(AS(buf, rbw, kb + lc));
                a[mt][1] = __float_as_uint(AS(buf, rbw + 8, kb + lc));
                a[mt][2] = __float_as_uint(AS(buf, rbw, kb + lc + 4));
                a[mt][3] = __float_as_uint(AS(buf, rbw + 8, kb + lc + 4));
            }
#pragma unroll
            for (int nt = 0; nt < 4; ++nt) {
                int nb = wn + nt * 8 + lr;
                b[nt][0] = __float_as_uint(BS(buf, nb, kb + lc));
                b[nt][1] = __float_as_uint(BS(buf, nb, kb + lc + 4));
            }
#pragma unroll
            for (int mt = 0; mt < 4; ++mt)
#pragma unroll
                for (int nt = 0; nt < 4; ++nt) MMA_TF32(acc[mt][nt], a[mt], b[nt]);
        }
        __syncthreads();
    }

#pragma unroll
    for (int mt = 0; mt < 4; ++mt) {
        int r0 = bm + wm + mt * 16 + lr;
#pragma unroll
        for (int nt = 0; nt < 4; ++nt) {
            int ccol = bn + wn + nt * 8 + 2 * lc;
            *(float2*)&C[(long)r0 * N + ccol] = make_float2(acc[mt][nt][0], acc[mt][nt][1]);
            *(float2*)&C[(long)(r0 + 8) * N + ccol] = make_float2(acc[mt][nt][2], acc[mt][nt][3]);
        }
    }
}

// ---------------------------------------------------------------------------
// Flash attention (causal), tf32 mma; K/V tiles register-prefetched so the
// next tile's LDG overlaps S/softmax/PV of the current tile.
// ---------------------------------------------------------------------------
#define QS_STRIDE 68
#define VS_STRIDE 72

__global__ void __launch_bounds__(128) attn_tf32(const float* __restrict__ qkv,
                                                 float* __restrict__ out) {
    extern __shared__ float sm[];
    float* Qs = sm;                              // [64][68]
    float* Ks = Qs + 64 * QS_STRIDE;             // [64][68]
    float* Vs = Ks + 64 * QS_STRIDE;             // [64][72]
    float* Ps = Vs + 64 * VS_STRIDE;             // [64][68]

    const int qt = blockIdx.x;
    const int h  = blockIdx.y;
    const int b  = blockIdx.z;
    const int tid = threadIdx.x;
    const int lane = tid & 31;
    const int wq = tid >> 5;
    const int lr = lane >> 2;
    const int lc = lane & 3;
    const int t0 = qt * 64;
    const float scale = 0.125f;

    const float* qbase = qkv + (long)b * TT * E3 + h * DHEAD;
    const float* kbase = qbase + TOTALE;
    const float* vbase = qbase + 2 * TOTALE;

#pragma unroll
    for (int i = 0; i < 8; ++i) {
        int idx = tid + i * 128;
        int r = idx >> 4, c4 = (idx & 15) << 2;
        float4 v = *(const float4*)&qbase[(long)(t0 + r) * E3 + c4];
        v.x = to_tf32(v.x * scale); v.y = to_tf32(v.y * scale);
        v.z = to_tf32(v.z * scale); v.w = to_tf32(v.w * scale);
        *(float4*)&Qs[r * QS_STRIDE + c4] = v;
    }

    float m0 = -CUDART_INF_F, m1 = -CUDART_INF_F, l0 = 0.f, l1 = 0.f;
    float o[8][4];
#pragma unroll
    for (int nt = 0; nt < 8; ++nt)
#pragma unroll
        for (int r = 0; r < 4; ++r) o[nt][r] = 0.f;

    float4 rk[8], rv[8];
#define ATTN_LDG(k0)                                                          \
    {                                                                         \
        _Pragma("unroll") for (int i = 0; i < 8; ++i) {                       \
            int idx = tid + i * 128;                                          \
            int r = idx >> 4, c4 = (idx & 15) << 2;                           \
            rk[i] = *(const float4*)&kbase[(long)((k0) + r) * E3 + c4];       \
            rv[i] = *(const float4*)&vbase[(long)((k0) + r) * E3 + c4];       \
        }                                                                     \
    }

    ATTN_LDG(0);

    for (int jt = 0; jt <= qt; ++jt) {
        __syncthreads();  // prior PV done with Ks/Vs (and Q load visible on iter 0)

        // stage prefetched K/V tile into smem (with tf32 rounding)
#pragma unroll
        for (int i = 0; i < 8; ++i) {
            int idx = tid + i * 128;
            int r = idx >> 4, c4 = (idx & 15) << 2;
            float4 vk = rk[i];
            vk.x = to_tf32(vk.x); vk.y = to_tf32(vk.y);
            vk.z = to_tf32(vk.z); vk.w = to_tf32(vk.w);
            *(float4*)&Ks[r * QS_STRIDE + c4] = vk;
            float4 vv = rv[i];
            vv.x = to_tf32(vv.x); vv.y = to_tf32(vv.y);
            vv.z = to_tf32(vv.z); vv.w = to_tf32(vv.w);
            *(float4*)&Vs[r * VS_STRIDE + c4] = vv;
        }
        if (jt < qt) ATTN_LDG((jt + 1) * 64);  // overlaps S/softmax/PV below
        __syncthreads();

        // ---- S = Q K^T
        float sacc[8][4];
#pragma unroll
        for (int nt = 0; nt < 8; ++nt)
#pragma unroll
            for (int r = 0; r < 4; ++r) sacc[nt][r] = 0.f;

#pragma unroll
        for (int ks = 0; ks < 8; ++ks) {
            const int kb = ks * 8;
            uint32_t a[4];
            int rb = wq * 16 + lr;
            a[0] = __float_as_uint(Qs[rb * QS_STRIDE + kb + lc]);
            a[1] = __float_as_uint(Qs[(rb + 8) * QS_STRIDE + kb + lc]);
            a[2] = __float_as_uint(Qs[rb * QS_STRIDE + kb + lc + 4]);
            a[3] = __float_as_uint(Qs[(rb + 8) * QS_STRIDE + kb + lc + 4]);
#pragma unroll
            for (int nt = 0; nt < 8; ++nt) {
                uint32_t bfr[2];
                int nb = nt * 8 + lr;
                bfr[0] = __float_as_uint(Ks[nb * QS_STRIDE + kb + lc]);
                bfr[1] = __float_as_uint(Ks[nb * QS_STRIDE + kb + lc + 4]);
                MMA_TF32(sacc[nt], a, bfr);
            }
        }

        // ---- causal mask (diagonal tile only)
        if (jt == qt) {
            int row0 = wq * 16 + lr, row1 = row0 + 8;
#pragma unroll
            for (int nt = 0; nt < 8; ++nt) {
                int col = nt * 8 + 2 * lc;
                if (col > row0)     sacc[nt][0] = -CUDART_INF_F;
                if (col + 1 > row0) sacc[nt][1] = -CUDART_INF_F;
                if (col > row1)     sacc[nt][2] = -CUDART_INF_F;
                if (col + 1 > row1) sacc[nt][3] = -CUDART_INF_F;
            }
        }

        // ---- online softmax
        float rm0 = -CUDART_INF_F, rm1 = -CUDART_INF_F;
#pragma unroll
        for (int nt = 0; nt < 8; ++nt) {
            rm0 = fmaxf(rm0, fmaxf(sacc[nt][0], sacc[nt][1]));
            rm1 = fmaxf(rm1, fmaxf(sacc[nt][2], sacc[nt][3]));
        }
        rm0 = fmaxf(rm0, __shfl_xor_sync(0xffffffffu, rm0, 1));
        rm0 = fmaxf(rm0, __shfl_xor_sync(0xffffffffu, rm0, 2));
        rm1 = fmaxf(rm1, __shfl_xor_sync(0xffffffffu, rm1, 1));
        rm1 = fmaxf(rm1, __shfl_xor_sync(0xffffffffu, rm1, 2));

        float mn0 = fmaxf(m0, rm0), mn1 = fmaxf(m1, rm1);
        float alpha0 = __expf(m0 - mn0), alpha1 = __expf(m1 - mn1);
        m0 = mn0; m1 = mn1;

        const int pr0 = wq * 16 + lr, pr1 = pr0 + 8;
        float rs0 = 0.f, rs1 = 0.f;
#pragma unroll
        for (int nt = 0; nt < 8; ++nt) {
            float p0 = __expf(sacc[nt][0] - mn0);
            float p1 = __expf(sacc[nt][1] - mn0);
            float p2 = __expf(sacc[nt][2] - mn1);
            float p3 = __expf(sacc[nt][3] - mn1);
            rs0 += p0 + p1; rs1 += p2 + p3;
            int cl = nt * 8 + 2 * lc;
            *(float2*)&Ps[pr0 * QS_STRIDE + cl] = make_float2(to_tf32(p0), to_tf32(p1));
            *(float2*)&Ps[pr1 * QS_STRIDE + cl] = make_float2(to_tf32(p2), to_tf32(p3));
        }
        rs0 += __shfl_xor_sync(0xffffffffu, rs0, 1);
        rs0 += __shfl_xor_sync(0xffffffffu, rs0, 2);
        rs1 += __shfl_xor_sync(0xffffffffu, rs1, 1);
        rs1 += __shfl_xor_sync(0xffffffffu, rs1, 2);
        l0 = l0 * alpha0 + rs0;
        l1 = l1 * alpha1 + rs1;
#pragma unroll
        for (int nt = 0; nt < 8; ++nt) {
            o[nt][0] *= alpha0; o[nt][1] *= alpha0;
            o[nt][2] *= alpha1; o[nt][3] *= alpha1;
        }
        __syncwarp();  // Ps rows are warp-private: order STS before LDS

        // ---- O += P V
#pragma unroll
        for (int ks = 0; ks < 8; ++ks) {
            const int kb = ks * 8;
            uint32_t a[4];
            int rb = wq * 16 + lr;
            a[0] = __float_as_uint(Ps[rb * QS_STRIDE + kb + lc]);
            a[1] = __float_as_uint(Ps[(rb + 8) * QS_STRIDE + kb + lc]);
            a[2] = __float_as_uint(Ps[rb * QS_STRIDE + kb + lc + 4]);
            a[3] = __float_as_uint(Ps[(rb + 8) * QS_STRIDE + kb + lc + 4]);
#pragma unroll
            for (int nt = 0; nt < 8; ++nt) {
                uint32_t bfr[2];
                bfr[0] = __float_as_uint(Vs[(kb + lc) * VS_STRIDE + nt * 8 + lr]);
                bfr[1] = __float_as_uint(Vs[(kb + lc + 4) * VS_STRIDE + nt * 8 + lr]);
                MMA_TF32(o[nt], a, bfr);
            }
        }
        __syncwarp();  // next iteration's Ps writes must not pass these reads
    }

    float inv0 = 1.f / l0, inv1 = 1.f / l1;
    int r0 = t0 + wq * 16 + lr, r1 = r0 + 8;
#pragma unroll
    for (int nt = 0; nt < 8; ++nt) {
        int d = h * DHEAD + nt * 8 + 2 * lc;
        *(float2*)&out[((long)b * TT + r0) * TOTALE + d] =
            make_float2(o[nt][0] * inv0, o[nt][1] * inv0);
        *(float2*)&out[((long)b * TT + r1) * TOTALE + d] =
            make_float2(o[nt][2] * inv1, o[nt][3] * inv1);
    }
}

// ---------------------------------------------------------------------------
extern "C" void kernel_launch(void* const* d_in, const int* in_sizes, int n_in,
                              void* d_out, int out_size) {
    const float* x    = (const float*)d_in[0];
    const float* Wqkv = (const float*)d_in[1];
    const float* Wout = (const float*)d_in[2];
    float* out = (float*)d_out;

    void *qkv_p, *att_p;
    cudaGetSymbolAddress(&qkv_p, g_qkv);
    cudaGetSymbolAddress(&att_p, g_att);
    float* qkv = (float*)qkv_p;
    float* att = (float*)att_p;

    const int M = BB * TT;
    const int gsmem = 2 * GSTAGE * (int)sizeof(float);  // 73728 B
    cudaFuncSetAttribute(gemm_tf32, cudaFuncAttributeMaxDynamicSharedMemorySize, gsmem);

    gemm_tf32<<<dim3(E3 / 128, M / 128), 256, gsmem>>>(x, Wqkv, qkv, M, E3, DMODEL);

    const int asmem = (64 * QS_STRIDE * 3 + 64 * VS_STRIDE) * sizeof(float);  // 70656 B
    cudaFuncSetAttribute(attn_tf32, cudaFuncAttributeMaxDynamicSharedMemorySize, asmem);
    attn_tf32<<<dim3(TT / 64, NHEADS, BB), 128, asmem>>>(qkv, att);

    gemm_tf32<<<dim3(DMODEL / 128, M / 128), 256, gsmem>>>(att, Wout, out, M, DMODEL, DMODEL);
}

// round 11
// speedup vs baseline: 1.1300x; 1.1300x over previous
#include <cstdint>
#include <cuda_runtime.h>
#include <cuda_bf16.h>
#include <math_constants.h>

#define BB     2
#define TT     2048
#define DMODEL 1024
#define NHEADS 16
#define DHEAD  64
#define TOTALE 1024
#define E3     3072

__device__ float g_qkv[BB * TT * E3];       // gemm1 out (tf32-rounded)
__device__ float g_att[BB * TT * TOTALE];   // attn out (tf32-rounded)
__device__ float g_xc[BB * TT * DMODEL];    // x, tf32-rounded
__device__ float g_wqkvc[E3 * DMODEL];      // Wqkv, tf32-rounded
__device__ float g_woutc[DMODEL * TOTALE];  // Wout, tf32-rounded

__device__ __forceinline__ float to_tf32(float x) {
    uint32_t r;
    asm("cvt.rna.tf32.f32 %0, %1;" : "=r"(r) : "f"(x));
    return __uint_as_float(r);
}

__device__ __forceinline__ void cp_async16(uint32_t saddr, const void* gptr) {
    asm volatile("cp.async.cg.shared.global [%0], [%1], 16;" :: "r"(saddr), "l"(gptr));
}
#define CP_COMMIT() asm volatile("cp.async.commit_group;" ::: "memory")
#define CP_WAIT1()  asm volatile("cp.async.wait_group 1;" ::: "memory")

#define MMA_TF32(d, a, b)                                                     \
    asm volatile("mma.sync.aligned.m16n8k8.row.col.f32.tf32.tf32.f32 "        \
                 "{%0,%1,%2,%3}, {%4,%5,%6,%7}, {%8,%9}, {%0,%1,%2,%3};"      \
                 : "+f"(d[0]), "+f"(d[1]), "+f"(d[2]), "+f"(d[3])             \
                 : "r"(a[0]), "r"(a[1]), "r"(a[2]), "r"(a[3]),                \
                   "r"(b[0]), "r"(b[1]))

// ---------------------------------------------------------------------------
// tf32 pre-round pass (float4 grid-stride)
// ---------------------------------------------------------------------------
__global__ void conv_tf32(const float* __restrict__ src, float* __restrict__ dst, int n4) {
    int i = blockIdx.x * blockDim.x + threadIdx.x;
    if (i < n4) {
        float4 v = ((const float4*)src)[i];
        v.x = to_tf32(v.x); v.y = to_tf32(v.y);
        v.z = to_tf32(v.z); v.w = to_tf32(v.w);
        ((float4*)dst)[i] = v;
    }
}

// ---------------------------------------------------------------------------
// tf32 GEMM, cp.async 3-stage pipeline. Operands pre-rounded (no cvt in loop).
// C[M,N] = A[M,K] @ B[N,K]^T. 128x128 tile, BK=32, 256 threads, 8 warps.
// ROUND_OUT: round C to tf32 (when C feeds a later tf32 GEMM/MMA).
// ---------------------------------------------------------------------------
#define ABUF 4608                 // 128*36 floats
#define GSTAGE 9216               // A+B per stage (floats)
#define AS(s, r, c) sh[(s) * GSTAGE + (r) * 36 + (c)]
#define BS(s, r, c) sh[(s) * GSTAGE + ABUF + (r) * 36 + (c)]

template <bool ROUND_OUT>
__global__ void __launch_bounds__(256, 2) gemm_tf32(const float* __restrict__ A,
                                                    const float* __restrict__ Bm,
                                                    float* __restrict__ C,
                                                    int M, int N, int K) {
    extern __shared__ float sh[];  // 3 * GSTAGE floats = 110592 B
    const uint32_t sbase = (uint32_t)__cvta_generic_to_shared(sh);

    const int tid = threadIdx.x;
    const int lane = tid & 31;
    const int w = tid >> 5;
    const int wm = (w >> 2) * 64;
    const int wn = (w & 3) * 32;
    const int bm = blockIdx.y * 128;
    const int bn = blockIdx.x * 128;
    const int lr = lane >> 2;
    const int lc = lane & 3;
    const int ldr = tid >> 3;          // 0..31
    const int ldc = (tid & 7) << 2;    // 0,4,..,28

    float acc[4][4][4];
#pragma unroll
    for (int i = 0; i < 4; ++i)
#pragma unroll
        for (int j = 0; j < 4; ++j)
#pragma unroll
            for (int r = 0; r < 4; ++r) acc[i][j][r] = 0.f;

#define GEMM_ISSUE(st, k0)                                                    \
    {                                                                         \
        _Pragma("unroll") for (int i = 0; i < 4; ++i) {                       \
            int r = ldr + i * 32;                                             \
            cp_async16(sbase + (uint32_t)(((st) * GSTAGE + r * 36 + ldc) * 4),\
                       &A[(long)(bm + r) * K + (k0) + ldc]);                  \
            cp_async16(sbase + (uint32_t)(((st) * GSTAGE + ABUF + r * 36 + ldc) * 4),\
                       &Bm[(long)(bn + r) * K + (k0) + ldc]);                 \
        }                                                                     \
        CP_COMMIT();                                                          \
    }

    const int nk = K >> 5;  // 32
    GEMM_ISSUE(0, 0);
    GEMM_ISSUE(1, 32);

    for (int it = 0; it < nk; ++it) {
        CP_WAIT1();          // stage `it` complete (own-thread view)
        __syncthreads();     // publish + all warps done with stage (it+2)%3's buffer
        if (it + 2 < nk) GEMM_ISSUE((it + 2) % 3, (it + 2) * 32);
        const int buf = it % 3;

#pragma unroll
        for (int ks = 0; ks < 4; ++ks) {
            const int kb = ks * 8;
            uint32_t a[4][4], b[4][2];
#pragma unroll
            for (int mt = 0; mt < 4; ++mt) {
                int rbw = wm + mt * 16 + lr;
                a[mt][0] = __float_as_uint(AS(buf, rbw, kb + lc));
                a[mt][1] = __float_as_uint(AS(buf, rbw + 8, kb + lc));
                a[mt][2] = __float_as_uint(AS(buf, rbw, kb + lc + 4));
                a[mt][3] = __float_as_uint(AS(buf, rbw + 8, kb + lc + 4));
            }
#pragma unroll
            for (int nt = 0; nt < 4; ++nt) {
                int nb = wn + nt * 8 + lr;
                b[nt][0] = __float_as_uint(BS(buf, nb, kb + lc));
                b[nt][1] = __float_as_uint(BS(buf, nb, kb + lc + 4));
            }
#pragma unroll
            for (int mt = 0; mt < 4; ++mt)
#pragma unroll
                for (int nt = 0; nt < 4; ++nt) MMA_TF32(acc[mt][nt], a[mt], b[nt]);
        }
    }

#pragma unroll
    for (int mt = 0; mt < 4; ++mt) {
        int r0 = bm + wm + mt * 16 + lr;
#pragma unroll
        for (int nt = 0; nt < 4; ++nt) {
            int ccol = bn + wn + nt * 8 + 2 * lc;
            float4 vals = make_float4(acc[mt][nt][0], acc[mt][nt][1],
                                      acc[mt][nt][2], acc[mt][nt][3]);
            if (ROUND_OUT) {
                vals.x = to_tf32(vals.x); vals.y = to_tf32(vals.y);
                vals.z = to_tf32(vals.z); vals.w = to_tf32(vals.w);
            }
            *(float2*)&C[(long)r0 * N + ccol] = make_float2(vals.x, vals.y);
            *(float2*)&C[(long)(r0 + 8) * N + ccol] = make_float2(vals.z, vals.w);
        }
    }
}

// ---------------------------------------------------------------------------
// Flash attention (causal), tf32 mma. R7 structure (direct LDG->STS staging).
// qkv is pre-rounded to tf32 by gemm1's epilogue -> no cvt at staging.
// Output rounded to tf32 (feeds gemm2's A operand).
// ---------------------------------------------------------------------------
#define QS_STRIDE 68
#define VS_STRIDE 72

__global__ void __launch_bounds__(128) attn_tf32(const float* __restrict__ qkv,
                                                 float* __restrict__ out) {
    extern __shared__ float sm[];
    float* Qs = sm;                              // [64][68]
    float* Ks = Qs + 64 * QS_STRIDE;             // [64][68]
    float* Vs = Ks + 64 * QS_STRIDE;             // [64][72]
    float* Ps = Vs + 64 * VS_STRIDE;             // [64][68]

    const int qt = blockIdx.x;
    const int h  = blockIdx.y;
    const int b  = blockIdx.z;
    const int tid = threadIdx.x;
    const int lane = tid & 31;
    const int wq = tid >> 5;
    const int lr = lane >> 2;
    const int lc = lane & 3;
    const int t0 = qt * 64;
    const float scale = 0.125f;  // power of 2: exact, commutes with tf32 rounding

    const float* qbase = qkv + (long)b * TT * E3 + h * DHEAD;
    const float* kbase = qbase + TOTALE;
    const float* vbase = qbase + 2 * TOTALE;

#pragma unroll
    for (int i = 0; i < 8; ++i) {
        int idx = tid + i * 128;
        int r = idx >> 4, c4 = (idx & 15) << 2;
        float4 v = *(const float4*)&qbase[(long)(t0 + r) * E3 + c4];
        v.x *= scale; v.y *= scale; v.z *= scale; v.w *= scale;
        *(float4*)&Qs[r * QS_STRIDE + c4] = v;
    }

    float m0 = -CUDART_INF_F, m1 = -CUDART_INF_F, l0 = 0.f, l1 = 0.f;
    float o[8][4];
#pragma unroll
    for (int nt = 0; nt < 8; ++nt)
#pragma unroll
        for (int r = 0; r < 4; ++r) o[nt][r] = 0.f;

    for (int jt = 0; jt <= qt; ++jt) {
        const int k0 = jt * 64;
        __syncthreads();  // prior PV done with Ks/Vs (and Q visible on iter 0)
#pragma unroll
        for (int i = 0; i < 8; ++i) {
            int idx = tid + i * 128;
            int r = idx >> 4, c4 = (idx & 15) << 2;
            *(float4*)&Ks[r * QS_STRIDE + c4] =
                *(const float4*)&kbase[(long)(k0 + r) * E3 + c4];
            *(float4*)&Vs[r * VS_STRIDE + c4] =
                *(const float4*)&vbase[(long)(k0 + r) * E3 + c4];
        }
        __syncthreads();

        // ---- S = Q K^T
        float sacc[8][4];
#pragma unroll
        for (int nt = 0; nt < 8; ++nt)
#pragma unroll
            for (int r = 0; r < 4; ++r) sacc[nt][r] = 0.f;

#pragma unroll
        for (int ks = 0; ks < 8; ++ks) {
            const int kb = ks * 8;
            uint32_t a[4];
            int rb = wq * 16 + lr;
            a[0] = __float_as_uint(Qs[rb * QS_STRIDE + kb + lc]);
            a[1] = __float_as_uint(Qs[(rb + 8) * QS_STRIDE + kb + lc]);
            a[2] = __float_as_uint(Qs[rb * QS_STRIDE + kb + lc + 4]);
            a[3] = __float_as_uint(Qs[(rb + 8) * QS_STRIDE + kb + lc + 4]);
#pragma unroll
            for (int nt = 0; nt < 8; ++nt) {
                uint32_t bfr[2];
                int nb = nt * 8 + lr;
                bfr[0] = __float_as_uint(Ks[nb * QS_STRIDE + kb + lc]);
                bfr[1] = __float_as_uint(Ks[nb * QS_STRIDE + kb + lc + 4]);
                MMA_TF32(sacc[nt], a, bfr);
            }
        }

        // ---- causal mask (diagonal tile only)
        if (jt == qt) {
            int row0 = wq * 16 + lr, row1 = row0 + 8;
#pragma unroll
            for (int nt = 0; nt < 8; ++nt) {
                int col = nt * 8 + 2 * lc;
                if (col > row0)     sacc[nt][0] = -CUDART_INF_F;
                if (col + 1 > row0) sacc[nt][1] = -CUDART_INF_F;
                if (col > row1)     sacc[nt][2] = -CUDART_INF_F;
                if (col + 1 > row1) sacc[nt][3] = -CUDART_INF_F;
            }
        }

        // ---- online softmax
        float rm0 = -CUDART_INF_F, rm1 = -CUDART_INF_F;
#pragma unroll
        for (int nt = 0; nt < 8; ++nt) {
            rm0 = fmaxf(rm0, fmaxf(sacc[nt][0], sacc[nt][1]));
            rm1 = fmaxf(rm1, fmaxf(sacc[nt][2], sacc[nt][3]));
        }
        rm0 = fmaxf(rm0, __shfl_xor_sync(0xffffffffu, rm0, 1));
        rm0 = fmaxf(rm0, __shfl_xor_sync(0xffffffffu, rm0, 2));
        rm1 = fmaxf(rm1, __shfl_xor_sync(0xffffffffu, rm1, 1));
        rm1 = fmaxf(rm1, __shfl_xor_sync(0xffffffffu, rm1, 2));

        float mn0 = fmaxf(m0, rm0), mn1 = fmaxf(m1, rm1);
        float alpha0 = __expf(m0 - mn0), alpha1 = __expf(m1 - mn1);
        m0 = mn0; m1 = mn1;

        const int pr0 = wq * 16 + lr, pr1 = pr0 + 8;
        float rs0 = 0.f, rs1 = 0.f;
#pragma unroll
        for (int nt = 0; nt < 8; ++nt) {
            float p0 = __expf(sacc[nt][0] - mn0);
            float p1 = __expf(sacc[nt][1] - mn0);
            float p2 = __expf(sacc[nt][2] - mn1);
            float p3 = __expf(sacc[nt][3] - mn1);
            rs0 += p0 + p1; rs1 += p2 + p3;
            int cl = nt * 8 + 2 * lc;
            *(float2*)&Ps[pr0 * QS_STRIDE + cl] = make_float2(to_tf32(p0), to_tf32(p1));
            *(float2*)&Ps[pr1 * QS_STRIDE + cl] = make_float2(to_tf32(p2), to_tf32(p3));
        }
        rs0 += __shfl_xor_sync(0xffffffffu, rs0, 1);
        rs0 += __shfl_xor_sync(0xffffffffu, rs0, 2);
        rs1 += __shfl_xor_sync(0xffffffffu, rs1, 1);
        rs1 += __shfl_xor_sync(0xffffffffu, rs1, 2);
        l0 = l0 * alpha0 + rs0;
        l1 = l1 * alpha1 + rs1;
#pragma unroll
        for (int nt = 0; nt < 8; ++nt) {
            o[nt][0] *= alpha0; o[nt][1] *= alpha0;
            o[nt][2] *= alpha1; o[nt][3] *= alpha1;
        }
        __syncwarp();  // Ps rows are warp-private: order STS before LDS

        // ---- O += P V
#pragma unroll
        for (int ks = 0; ks < 8; ++ks) {
            const int kb = ks * 8;
            uint32_t a[4];
            int rb = wq * 16 + lr;
            a[0] = __float_as_uint(Ps[rb * QS_STRIDE + kb + lc]);
            a[1] = __float_as_uint(Ps[(rb + 8) * QS_STRIDE + kb + lc]);
            a[2] = __float_as_uint(Ps[rb * QS_STRIDE + kb + lc + 4]);
            a[3] = __float_as_uint(Ps[(rb + 8) * QS_STRIDE + kb + lc + 4]);
#pragma unroll
            for (int nt = 0; nt < 8; ++nt) {
                uint32_t bfr[2];
                bfr[0] = __float_as_uint(Vs[(kb + lc) * VS_STRIDE + nt * 8 + lr]);
                bfr[1] = __float_as_uint(Vs[(kb + lc + 4) * VS_STRIDE + nt * 8 + lr]);
                MMA_TF32(o[nt], a, bfr);
            }
        }
        __syncwarp();  // next iteration's Ps writes must not pass these reads
    }

    // ---- epilogue (rounded: feeds tf32 gemm2)
    float inv0 = 1.f / l0, inv1 = 1.f / l1;
    int r0 = t0 + wq * 16 + lr, r1 = r0 + 8;
#pragma unroll
    for (int nt = 0; nt < 8; ++nt) {
        int d = h * DHEAD + nt * 8 + 2 * lc;
        *(float2*)&out[((long)b * TT + r0) * TOTALE + d] =
            make_float2(to_tf32(o[nt][0] * inv0), to_tf32(o[nt][1] * inv0));
        *(float2*)&out[((long)b * TT + r1) * TOTALE + d] =
            make_float2(to_tf32(o[nt][2] * inv1), to_tf32(o[nt][3] * inv1));
    }
}

// ---------------------------------------------------------------------------
extern "C" void kernel_launch(void* const* d_in, const int* in_sizes, int n_in,
                              void* d_out, int out_size) {
    const float* x    = (const float*)d_in[0];
    const float* Wqkv = (const float*)d_in[1];
    const float* Wout = (const float*)d_in[2];
    float* out = (float*)d_out;

    void *qkv_p, *att_p, *xc_p, *wq_p, *wo_p;
    cudaGetSymbolAddress(&qkv_p, g_qkv);
    cudaGetSymbolAddress(&att_p, g_att);
    cudaGetSymbolAddress(&xc_p, g_xc);
    cudaGetSymbolAddress(&wq_p, g_wqkvc);
    cudaGetSymbolAddress(&wo_p, g_woutc);
    float* qkv = (float*)qkv_p;
    float* att = (float*)att_p;
    float* xc  = (float*)xc_p;
    float* wqc = (float*)wq_p;
    float* woc = (float*)wo_p;

    const int M = BB * TT;

    // Pre-round operands to tf32
    conv_tf32<<<(M * DMODEL / 4 + 255) / 256, 256>>>(x, xc, M * DMODEL / 4);
    conv_tf32<<<(E3 * DMODEL / 4 + 255) / 256, 256>>>(Wqkv, wqc, E3 * DMODEL / 4);
    conv_tf32<<<(DMODEL * TOTALE / 4 + 255) / 256, 256>>>(Wout, woc, DMODEL * TOTALE / 4);

    const int gsmem = 3 * GSTAGE * (int)sizeof(float);  // 110592 B
    cudaFuncSetAttribute(gemm_tf32<true>,  cudaFuncAttributeMaxDynamicSharedMemorySize, gsmem);
    cudaFuncSetAttribute(gemm_tf32<false>, cudaFuncAttributeMaxDynamicSharedMemorySize, gsmem);

    gemm_tf32<true><<<dim3(E3 / 128, M / 128), 256, gsmem>>>(xc, wqc, qkv, M, E3, DMODEL);

    const int asmem = (64 * QS_STRIDE * 3 + 64 * VS_STRIDE) * sizeof(float);  // 70656 B
    cudaFuncSetAttribute(attn_tf32, cudaFuncAttributeMaxDynamicSharedMemorySize, asmem);
    attn_tf32<<<dim3(TT / 64, NHEADS, BB), 128, asmem>>>(qkv, att);

    gemm_tf32<false><<<dim3(DMODEL / 128, M / 128), 256, gsmem>>>(att, woc, out, M, DMODEL, DMODEL);
}

// round 12
// speedup vs baseline: 1.1964x; 1.0587x over previous
#include <cstdint>
#include <cuda_runtime.h>
#include <cuda_bf16.h>
#include <math_constants.h>

#define BB     2
#define TT     2048
#define DMODEL 1024
#define NHEADS 16
#define DHEAD  64
#define TOTALE 1024
#define E3     3072

__device__ float g_qkv[BB * TT * E3];       // gemm1 out (tf32-rounded)
__device__ float g_att[BB * TT * TOTALE];   // attn out (tf32-rounded)
__device__ float g_xc[BB * TT * DMODEL];    // x, tf32-rounded
__device__ float g_wqkvc[E3 * DMODEL];      // Wqkv, tf32-rounded
__device__ float g_woutc[DMODEL * TOTALE];  // Wout, tf32-rounded

__device__ __forceinline__ float to_tf32(float x) {
    uint32_t r;
    asm("cvt.rna.tf32.f32 %0, %1;" : "=r"(r) : "f"(x));
    return __uint_as_float(r);
}

__device__ __forceinline__ void cp_async16(uint32_t saddr, const void* gptr) {
    asm volatile("cp.async.cg.shared.global [%0], [%1], 16;" :: "r"(saddr), "l"(gptr));
}
#define CP_COMMIT() asm volatile("cp.async.commit_group;" ::: "memory")
#define CP_WAIT1()  asm volatile("cp.async.wait_group 1;" ::: "memory")

#define MMA_TF32(d, a, b)                                                     \
    asm volatile("mma.sync.aligned.m16n8k8.row.col.f32.tf32.tf32.f32 "        \
                 "{%0,%1,%2,%3}, {%4,%5,%6,%7}, {%8,%9}, {%0,%1,%2,%3};"      \
                 : "+f"(d[0]), "+f"(d[1]), "+f"(d[2]), "+f"(d[3])             \
                 : "r"(a[0]), "r"(a[1]), "r"(a[2]), "r"(a[3]),                \
                   "r"(b[0]), "r"(b[1]))

#define LDMATRIX_X4(r0, r1, r2, r3, addr)                                     \
    asm volatile("ldmatrix.sync.aligned.m8n8.x4.shared.b16 {%0,%1,%2,%3}, [%4];" \
                 : "=r"(r0), "=r"(r1), "=r"(r2), "=r"(r3) : "r"(addr))

// ---------------------------------------------------------------------------
// tf32 pre-round pass (float4 grid-stride)
// ---------------------------------------------------------------------------
__global__ void conv_tf32(const float* __restrict__ src, float* __restrict__ dst, int n4) {
    int i = blockIdx.x * blockDim.x + threadIdx.x;
    if (i < n4) {
        float4 v = ((const float4*)src)[i];
        v.x = to_tf32(v.x); v.y = to_tf32(v.y);
        v.z = to_tf32(v.z); v.w = to_tf32(v.w);
        ((float4*)dst)[i] = v;
    }
}

// ---------------------------------------------------------------------------
// tf32 GEMM, cp.async 3-stage pipeline + ldmatrix fragment loads.
// C[M,N] = A[M,K] @ B[N,K]^T. 128x128 tile, BK=32, 256 threads, 8 warps.
// ---------------------------------------------------------------------------
#define ABUF 4608                 // 128*36 floats
#define GSTAGE 9216               // A+B per stage (floats)

template <bool ROUND_OUT>
__global__ void __launch_bounds__(256, 2) gemm_tf32(const float* __restrict__ A,
                                                    const float* __restrict__ Bm,
                                                    float* __restrict__ C,
                                                    int M, int N, int K) {
    extern __shared__ float sh[];  // 3 * GSTAGE floats = 110592 B
    const uint32_t sbase = (uint32_t)__cvta_generic_to_shared(sh);

    const int tid = threadIdx.x;
    const int lane = tid & 31;
    const int w = tid >> 5;
    const int wm = (w >> 2) * 64;
    const int wn = (w & 3) * 32;
    const int bm = blockIdx.y * 128;
    const int bn = blockIdx.x * 128;
    const int lr = lane >> 2;
    const int lc = lane & 3;
    const int ldr = tid >> 3;          // 0..31
    const int ldc = (tid & 7) << 2;    // 0,4,..,28

    // ldmatrix per-lane source offsets (floats, within a stage buffer)
    //  A frag (16x8 tf32 tile): lanes 0-15 -> rows, lanes 16-31 -> col+4
    const int a_off = (wm + (lane & 15)) * 36 + ((lane >> 4) << 2);
    //  B frags, two n-tiles per x4: lanes {0-7,8-15}=rows nb..nb+7 col {0,+4},
    //  lanes {16-23,24-31}=rows nb+8..nb+15 col {0,+4}
    const int b_off = ABUF + (wn + ((lane >> 4) << 3) + (lane & 7)) * 36 + ((lane & 8) ? 4 : 0);

    float acc[4][4][4];
#pragma unroll
    for (int i = 0; i < 4; ++i)
#pragma unroll
        for (int j = 0; j < 4; ++j)
#pragma unroll
            for (int r = 0; r < 4; ++r) acc[i][j][r] = 0.f;

#define GEMM_ISSUE(st, k0)                                                    \
    {                                                                         \
        _Pragma("unroll") for (int i = 0; i < 4; ++i) {                       \
            int r = ldr + i * 32;                                             \
            cp_async16(sbase + (uint32_t)(((st) * GSTAGE + r * 36 + ldc) * 4),\
                       &A[(long)(bm + r) * K + (k0) + ldc]);                  \
            cp_async16(sbase + (uint32_t)(((st) * GSTAGE + ABUF + r * 36 + ldc) * 4),\
                       &Bm[(long)(bn + r) * K + (k0) + ldc]);                 \
        }                                                                     \
        CP_COMMIT();                                                          \
    }

    const int nk = K >> 5;  // 32
    GEMM_ISSUE(0, 0);
    GEMM_ISSUE(1, 32);

    for (int it = 0; it < nk; ++it) {
        CP_WAIT1();          // stage `it` complete (own-thread view)
        __syncthreads();     // publish + all warps done with stage (it+2)%3's buffer
        if (it + 2 < nk) GEMM_ISSUE((it + 2) % 3, (it + 2) * 32);
        const uint32_t bufbase = sbase + (uint32_t)((it % 3) * GSTAGE * 4);

#pragma unroll
        for (int ks = 0; ks < 4; ++ks) {
            const int kb = ks * 8;
            uint32_t a[4][4], b[4][2];
#pragma unroll
            for (int mt = 0; mt < 4; ++mt) {
                uint32_t addr = bufbase + (uint32_t)((a_off + mt * 16 * 36 + kb) * 4);
                LDMATRIX_X4(a[mt][0], a[mt][1], a[mt][2], a[mt][3], addr);
            }
#pragma unroll
            for (int p = 0; p < 2; ++p) {
                uint32_t addr = bufbase + (uint32_t)((b_off + p * 16 * 36 + kb) * 4);
                LDMATRIX_X4(b[2 * p][0], b[2 * p][1], b[2 * p + 1][0], b[2 * p + 1][1], addr);
            }
#pragma unroll
            for (int mt = 0; mt < 4; ++mt)
#pragma unroll
                for (int nt = 0; nt < 4; ++nt) MMA_TF32(acc[mt][nt], a[mt], b[nt]);
        }
    }

#pragma unroll
    for (int mt = 0; mt < 4; ++mt) {
        int r0 = bm + wm + mt * 16 + lr;
#pragma unroll
        for (int nt = 0; nt < 4; ++nt) {
            int ccol = bn + wn + nt * 8 + 2 * lc;
            float4 vals = make_float4(acc[mt][nt][0], acc[mt][nt][1],
                                      acc[mt][nt][2], acc[mt][nt][3]);
            if (ROUND_OUT) {
                vals.x = to_tf32(vals.x); vals.y = to_tf32(vals.y);
                vals.z = to_tf32(vals.z); vals.w = to_tf32(vals.w);
            }
            *(float2*)&C[(long)r0 * N + ccol] = make_float2(vals.x, vals.y);
            *(float2*)&C[(long)(r0 + 8) * N + ccol] = make_float2(vals.z, vals.w);
        }
    }
}

// ---------------------------------------------------------------------------
// Flash attention (causal), tf32 mma. Unchanged from R11 (best config).
// ---------------------------------------------------------------------------
#define QS_STRIDE 68
#define VS_STRIDE 72

__global__ void __launch_bounds__(128) attn_tf32(const float* __restrict__ qkv,
                                                 float* __restrict__ out) {
    extern __shared__ float sm[];
    float* Qs = sm;                              // [64][68]
    float* Ks = Qs + 64 * QS_STRIDE;             // [64][68]
    float* Vs = Ks + 64 * QS_STRIDE;             // [64][72]
    float* Ps = Vs + 64 * VS_STRIDE;             // [64][68]

    const int qt = blockIdx.x;
    const int h  = blockIdx.y;
    const int b  = blockIdx.z;
    const int tid = threadIdx.x;
    const int lane = tid & 31;
    const int wq = tid >> 5;
    const int lr = lane >> 2;
    const int lc = lane & 3;
    const int t0 = qt * 64;
    const float scale = 0.125f;  // power of 2: exact, commutes with tf32 rounding

    const float* qbase = qkv + (long)b * TT * E3 + h * DHEAD;
    const float* kbase = qbase + TOTALE;
    const float* vbase = qbase + 2 * TOTALE;

#pragma unroll
    for (int i = 0; i < 8; ++i) {
        int idx = tid + i * 128;
        int r = idx >> 4, c4 = (idx & 15) << 2;
        float4 v = *(const float4*)&qbase[(long)(t0 + r) * E3 + c4];
        v.x *= scale; v.y *= scale; v.z *= scale; v.w *= scale;
        *(float4*)&Qs[r * QS_STRIDE + c4] = v;
    }

    float m0 = -CUDART_INF_F, m1 = -CUDART_INF_F, l0 = 0.f, l1 = 0.f;
    float o[8][4];
#pragma unroll
    for (int nt = 0; nt < 8; ++nt)
#pragma unroll
        for (int r = 0; r < 4; ++r) o[nt][r] = 0.f;

    for (int jt = 0; jt <= qt; ++jt) {
        const int k0 = jt * 64;
        __syncthreads();  // prior PV done with Ks/Vs (and Q visible on iter 0)
#pragma unroll
        for (int i = 0; i < 8; ++i) {
            int idx = tid + i * 128;
            int r = idx >> 4, c4 = (idx & 15) << 2;
            *(float4*)&Ks[r * QS_STRIDE + c4] =
                *(const float4*)&kbase[(long)(k0 + r) * E3 + c4];
            *(float4*)&Vs[r * VS_STRIDE + c4] =
                *(const float4*)&vbase[(long)(k0 + r) * E3 + c4];
        }
        __syncthreads();

        // ---- S = Q K^T
        float sacc[8][4];
#pragma unroll
        for (int nt = 0; nt < 8; ++nt)
#pragma unroll
            for (int r = 0; r < 4; ++r) sacc[nt][r] = 0.f;

#pragma unroll
        for (int ks = 0; ks < 8; ++ks) {
            const int kb = ks * 8;
            uint32_t a[4];
            int rb = wq * 16 + lr;
            a[0] = __float_as_uint(Qs[rb * QS_STRIDE + kb + lc]);
            a[1] = __float_as_uint(Qs[(rb + 8) * QS_STRIDE + kb + lc]);
            a[2] = __float_as_uint(Qs[rb * QS_STRIDE + kb + lc + 4]);
            a[3] = __float_as_uint(Qs[(rb + 8) * QS_STRIDE + kb + lc + 4]);
#pragma unroll
            for (int nt = 0; nt < 8; ++nt) {
                uint32_t bfr[2];
                int nb = nt * 8 + lr;
                bfr[0] = __float_as_uint(Ks[nb * QS_STRIDE + kb + lc]);
                bfr[1] = __float_as_uint(Ks[nb * QS_STRIDE + kb + lc + 4]);
                MMA_TF32(sacc[nt], a, bfr);
            }
        }

        // ---- causal mask (diagonal tile only)
        if (jt == qt) {
            int row0 = wq * 16 + lr, row1 = row0 + 8;
#pragma unroll
            for (int nt = 0; nt < 8; ++nt) {
                int col = nt * 8 + 2 * lc;
                if (col > row0)     sacc[nt][0] = -CUDART_INF_F;
                if (col + 1 > row0) sacc[nt][1] = -CUDART_INF_F;
                if (col > row1)     sacc[nt][2] = -CUDART_INF_F;
                if (col + 1 > row1) sacc[nt][3] = -CUDART_INF_F;
            }
        }

        // ---- online softmax
        float rm0 = -CUDART_INF_F, rm1 = -CUDART_INF_F;
#pragma unroll
        for (int nt = 0; nt < 8; ++nt) {
            rm0 = fmaxf(rm0, fmaxf(sacc[nt][0], sacc[nt][1]));
            rm1 = fmaxf(rm1, fmaxf(sacc[nt][2], sacc[nt][3]));
        }
        rm0 = fmaxf(rm0, __shfl_xor_sync(0xffffffffu, rm0, 1));
        rm0 = fmaxf(rm0, __shfl_xor_sync(0xffffffffu, rm0, 2));
        rm1 = fmaxf(rm1, __shfl_xor_sync(0xffffffffu, rm1, 1));
        rm1 = fmaxf(rm1, __shfl_xor_sync(0xffffffffu, rm1, 2));

        float mn0 = fmaxf(m0, rm0), mn1 = fmaxf(m1, rm1);
        float alpha0 = __expf(m0 - mn0), alpha1 = __expf(m1 - mn1);
        m0 = mn0; m1 = mn1;

        const int pr0 = wq * 16 + lr, pr1 = pr0 + 8;
        float rs0 = 0.f, rs1 = 0.f;
#pragma unroll
        for (int nt = 0; nt < 8; ++nt) {
            float p0 = __expf(sacc[nt][0] - mn0);
            float p1 = __expf(sacc[nt][1] - mn0);
            float p2 = __expf(sacc[nt][2] - mn1);
            float p3 = __expf(sacc[nt][3] - mn1);
            rs0 += p0 + p1; rs1 += p2 + p3;
            int cl = nt * 8 + 2 * lc;
            *(float2*)&Ps[pr0 * QS_STRIDE + cl] = make_float2(to_tf32(p0), to_tf32(p1));
            *(float2*)&Ps[pr1 * QS_STRIDE + cl] = make_float2(to_tf32(p2), to_tf32(p3));
        }
        rs0 += __shfl_xor_sync(0xffffffffu, rs0, 1);
        rs0 += __shfl_xor_sync(0xffffffffu, rs0, 2);
        rs1 += __shfl_xor_sync(0xffffffffu, rs1, 1);
        rs1 += __shfl_xor_sync(0xffffffffu, rs1, 2);
        l0 = l0 * alpha0 + rs0;
        l1 = l1 * alpha1 + rs1;
#pragma unroll
        for (int nt = 0; nt < 8; ++nt) {
            o[nt][0] *= alpha0; o[nt][1] *= alpha0;
            o[nt][2] *= alpha1; o[nt][3] *= alpha1;
        }
        __syncwarp();  // Ps rows are warp-private: order STS before LDS

        // ---- O += P V
#pragma unroll
        for (int ks = 0; ks < 8; ++ks) {
            const int kb = ks * 8;
            uint32_t a[4];
            int rb = wq * 16 + lr;
            a[0] = __float_as_uint(Ps[rb * QS_STRIDE + kb + lc]);
            a[1] = __float_as_uint(Ps[(rb + 8) * QS_STRIDE + kb + lc]);
            a[2] = __float_as_uint(Ps[rb * QS_STRIDE + kb + lc + 4]);
            a[3] = __float_as_uint(Ps[(rb + 8) * QS_STRIDE + kb + lc + 4]);
#pragma unroll
            for (int nt = 0; nt < 8; ++nt) {
                uint32_t bfr[2];
                bfr[0] = __float_as_uint(Vs[(kb + lc) * VS_STRIDE + nt * 8 + lr]);
                bfr[1] = __float_as_uint(Vs[(kb + lc + 4) * VS_STRIDE + nt * 8 + lr]);
                MMA_TF32(o[nt], a, bfr);
            }
        }
        __syncwarp();  // next iteration's Ps writes must not pass these reads
    }

    // ---- epilogue (rounded: feeds tf32 gemm2)
    float inv0 = 1.f / l0, inv1 = 1.f / l1;
    int r0 = t0 + wq * 16 + lr, r1 = r0 + 8;
#pragma unroll
    for (int nt = 0; nt < 8; ++nt) {
        int d = h * DHEAD + nt * 8 + 2 * lc;
        *(float2*)&out[((long)b * TT + r0) * TOTALE + d] =
            make_float2(to_tf32(o[nt][0] * inv0), to_tf32(o[nt][1] * inv0));
        *(float2*)&out[((long)b * TT + r1) * TOTALE + d] =
            make_float2(to_tf32(o[nt][2] * inv1), to_tf32(o[nt][3] * inv1));
    }
}

// ---------------------------------------------------------------------------
extern "C" void kernel_launch(void* const* d_in, const int* in_sizes, int n_in,
                              void* d_out, int out_size) {
    const float* x    = (const float*)d_in[0];
    const float* Wqkv = (const float*)d_in[1];
    const float* Wout = (const float*)d_in[2];
    float* out = (float*)d_out;

    void *qkv_p, *att_p, *xc_p, *wq_p, *wo_p;
    cudaGetSymbolAddress(&qkv_p, g_qkv);
    cudaGetSymbolAddress(&att_p, g_att);
    cudaGetSymbolAddress(&xc_p, g_xc);
    cudaGetSymbolAddress(&wq_p, g_wqkvc);
    cudaGetSymbolAddress(&wo_p, g_woutc);
    float* qkv = (float*)qkv_p;
    float* att = (float*)att_p;
    float* xc  = (float*)xc_p;
    float* wqc = (float*)wq_p;
    float* woc = (float*)wo_p;

    const int M = BB * TT;

    conv_tf32<<<(M * DMODEL / 4 + 255) / 256, 256>>>(x, xc, M * DMODEL / 4);
    conv_tf32<<<(E3 * DMODEL / 4 + 255) / 256, 256>>>(Wqkv, wqc, E3 * DMODEL / 4);
    conv_tf32<<<(DMODEL * TOTALE / 4 + 255) / 256, 256>>>(Wout, woc, DMODEL * TOTALE / 4);

    const int gsmem = 3 * GSTAGE * (int)sizeof(float);  // 110592 B
    cudaFuncSetAttribute(gemm_tf32<true>,  cudaFuncAttributeMaxDynamicSharedMemorySize, gsmem);
    cudaFuncSetAttribute(gemm_tf32<false>, cudaFuncAttributeMaxDynamicSharedMemorySize, gsmem);

    gemm_tf32<true><<<dim3(E3 / 128, M / 128), 256, gsmem>>>(xc, wqc, qkv, M, E3, DMODEL);

    const int asmem = (64 * QS_STRIDE * 3 + 64 * VS_STRIDE) * sizeof(float);  // 70656 B
    cudaFuncSetAttribute(attn_tf32, cudaFuncAttributeMaxDynamicSharedMemorySize, asmem);
    attn_tf32<<<dim3(TT / 64, NHEADS, BB), 128, asmem>>>(qkv, att);

    gemm_tf32<false><<<dim3(DMODEL / 128, M / 128), 256, gsmem>>>(att, woc, out, M, DMODEL, DMODEL);
}

// round 16
// speedup vs baseline: 1.2166x; 1.0169x over previous
#include <cstdint>
#include <cuda_runtime.h>
#include <cuda_bf16.h>
#include <math_constants.h>

#define BB     2
#define TT     2048
#define DMODEL 1024
#define NHEADS 16
#define DHEAD  64
#define TOTALE 1024
#define E3     3072

__device__ float g_qkv[BB * TT * E3];       // gemm1 out (tf32-rounded)
__device__ float g_att[BB * TT * TOTALE];   // attn out (tf32-rounded)
__device__ float g_xc[BB * TT * DMODEL];    // x, tf32-rounded
__device__ float g_wqkvc[E3 * DMODEL];      // Wqkv, tf32-rounded
__device__ float g_woutc[DMODEL * TOTALE];  // Wout, tf32-rounded

__device__ __forceinline__ float to_tf32(float x) {
    uint32_t r;
    asm("cvt.rna.tf32.f32 %0, %1;" : "=r"(r) : "f"(x));
    return __uint_as_float(r);
}

__device__ __forceinline__ void cp_async16(uint32_t saddr, const void* gptr) {
    asm volatile("cp.async.cg.shared.global [%0], [%1], 16;" :: "r"(saddr), "l"(gptr));
}
#define CP_COMMIT() asm volatile("cp.async.commit_group;" ::: "memory")
#define CP_WAIT1()  asm volatile("cp.async.wait_group 1;" ::: "memory")

#define MMA_TF32(d, a, b)                                                     \
    asm volatile("mma.sync.aligned.m16n8k8.row.col.f32.tf32.tf32.f32 "        \
                 "{%0,%1,%2,%3}, {%4,%5,%6,%7}, {%8,%9}, {%0,%1,%2,%3};"      \
                 : "+f"(d[0]), "+f"(d[1]), "+f"(d[2]), "+f"(d[3])             \
                 : "r"(a[0]), "r"(a[1]), "r"(a[2]), "r"(a[3]),                \
                   "r"(b[0]), "r"(b[1]))

#define LDMATRIX_X4(r0, r1, r2, r3, addr)                                     \
    asm volatile("ldmatrix.sync.aligned.m8n8.x4.shared.b16 {%0,%1,%2,%3}, [%4];" \
                 : "=r"(r0), "=r"(r1), "=r"(r2), "=r"(r3) : "r"(addr))

// ---------------------------------------------------------------------------
// tf32 pre-round pass
// ---------------------------------------------------------------------------
__global__ void conv_tf32(const float* __restrict__ src, float* __restrict__ dst, int n4) {
    int i = blockIdx.x * blockDim.x + threadIdx.x;
    if (i < n4) {
        float4 v = ((const float4*)src)[i];
        v.x = to_tf32(v.x); v.y = to_tf32(v.y);
        v.z = to_tf32(v.z); v.w = to_tf32(v.w);
        ((float4*)dst)[i] = v;
    }
}

// ---------------------------------------------------------------------------
// tf32 GEMM (unchanged from R12): cp.async 3-stage + ldmatrix.
// ---------------------------------------------------------------------------
#define ABUF 4608
#define GSTAGE 9216

template <bool ROUND_OUT>
__global__ void __launch_bounds__(256, 2) gemm_tf32(const float* __restrict__ A,
                                                    const float* __restrict__ Bm,
                                                    float* __restrict__ C,
                                                    int M, int N, int K) {
    extern __shared__ float sh[];
    const uint32_t sbase = (uint32_t)__cvta_generic_to_shared(sh);

    const int tid = threadIdx.x;
    const int lane = tid & 31;
    const int w = tid >> 5;
    const int wm = (w >> 2) * 64;
    const int wn = (w & 3) * 32;
    const int bm = blockIdx.y * 128;
    const int bn = blockIdx.x * 128;
    const int lr = lane >> 2;
    const int lc = lane & 3;
    const int ldr = tid >> 3;
    const int ldc = (tid & 7) << 2;

    const int a_off = (wm + (lane & 15)) * 36 + ((lane >> 4) << 2);
    const int b_off = ABUF + (wn + ((lane >> 4) << 3) + (lane & 7)) * 36 + ((lane & 8) ? 4 : 0);

    float acc[4][4][4];
#pragma unroll
    for (int i = 0; i < 4; ++i)
#pragma unroll
        for (int j = 0; j < 4; ++j)
#pragma unroll
            for (int r = 0; r < 4; ++r) acc[i][j][r] = 0.f;

#define GEMM_ISSUE(st, k0)                                                    \
    {                                                                         \
        _Pragma("unroll") for (int i = 0; i < 4; ++i) {                       \
            int r = ldr + i * 32;                                             \
            cp_async16(sbase + (uint32_t)(((st) * GSTAGE + r * 36 + ldc) * 4),\
                       &A[(long)(bm + r) * K + (k0) + ldc]);                  \
            cp_async16(sbase + (uint32_t)(((st) * GSTAGE + ABUF + r * 36 + ldc) * 4),\
                       &Bm[(long)(bn + r) * K + (k0) + ldc]);                 \
        }                                                                     \
        CP_COMMIT();                                                          \
    }

    const int nk = K >> 5;
    GEMM_ISSUE(0, 0);
    GEMM_ISSUE(1, 32);

    for (int it = 0; it < nk; ++it) {
        CP_WAIT1();
        __syncthreads();
        if (it + 2 < nk) GEMM_ISSUE((it + 2) % 3, (it + 2) * 32);
        const uint32_t bufbase = sbase + (uint32_t)((it % 3) * GSTAGE * 4);

#pragma unroll
        for (int ks = 0; ks < 4; ++ks) {
            const int kb = ks * 8;
            uint32_t a[4][4], b[4][2];
#pragma unroll
            for (int mt = 0; mt < 4; ++mt) {
                uint32_t addr = bufbase + (uint32_t)((a_off + mt * 16 * 36 + kb) * 4);
                LDMATRIX_X4(a[mt][0], a[mt][1], a[mt][2], a[mt][3], addr);
            }
#pragma unroll
            for (int p = 0; p < 2; ++p) {
                uint32_t addr = bufbase + (uint32_t)((b_off + p * 16 * 36 + kb) * 4);
                LDMATRIX_X4(b[2 * p][0], b[2 * p][1], b[2 * p + 1][0], b[2 * p + 1][1], addr);
            }
#pragma unroll
            for (int mt = 0; mt < 4; ++mt)
#pragma unroll
                for (int nt = 0; nt < 4; ++nt) MMA_TF32(acc[mt][nt], a[mt], b[nt]);
        }
    }

#pragma unroll
    for (int mt = 0; mt < 4; ++mt) {
        int r0 = bm + wm + mt * 16 + lr;
#pragma unroll
        for (int nt = 0; nt < 4; ++nt) {
            int ccol = bn + wn + nt * 8 + 2 * lc;
            float4 vals = make_float4(acc[mt][nt][0], acc[mt][nt][1],
                                      acc[mt][nt][2], acc[mt][nt][3]);
            if (ROUND_OUT) {
                vals.x = to_tf32(vals.x); vals.y = to_tf32(vals.y);
                vals.z = to_tf32(vals.z); vals.w = to_tf32(vals.w);
            }
            *(float2*)&C[(long)r0 * N + ccol] = make_float2(vals.x, vals.y);
            *(float2*)&C[(long)(r0 + 8) * N + ccol] = make_float2(vals.z, vals.w);
        }
    }
}

// ---------------------------------------------------------------------------
// Flash attention: Q frags hoisted to regs, ldmatrix for K/P/V, V transposed.
// smem = Ks[64][68] + Vt[64][68] + Ps[64][68] = 52224 B -> 4 CTAs/SM.
// ---------------------------------------------------------------------------
#define AST 68  // attention smem stride

__global__ void __launch_bounds__(128) attn_tf32(const float* __restrict__ qkv,
                                                 float* __restrict__ out) {
    extern __shared__ float sm[];
    float* Ks = sm;                   // [64][68] (also Q staging buffer)
    float* Vt = Ks + 64 * AST;        // [64][68]  rows=d, cols=kpos
    float* Ps = Vt + 64 * AST;        // [64][68]
    const uint32_t ks_base = (uint32_t)__cvta_generic_to_shared(Ks);
    const uint32_t vt_base = (uint32_t)__cvta_generic_to_shared(Vt);
    const uint32_t ps_base = (uint32_t)__cvta_generic_to_shared(Ps);

    const int qt = blockIdx.x;
    const int h  = blockIdx.y;
    const int b  = blockIdx.z;
    const int tid = threadIdx.x;
    const int lane = tid & 31;
    const int wq = tid >> 5;
    const int lr = lane >> 2;
    const int lc = lane & 3;
    const int t0 = qt * 64;
    const float scale = 0.125f;  // 2^-3: exact

    const float* qbase = qkv + (long)b * TT * E3 + h * DHEAD;
    const float* kbase = qbase + TOTALE;
    const float* vbase = qbase + 2 * TOTALE;

    // per-lane ldmatrix offsets (floats)
    const int afrag_off = ((lane & 15)) * AST + ((lane >> 4) << 2);  // + row_base*AST + kb
    const int bfrag_off = (((lane >> 4) << 3) + (lane & 7)) * AST + ((lane & 8) ? 4 : 0);

    // ---- stage Q (scaled) into Ks buffer, hoist fragments to registers
#pragma unroll
    for (int i = 0; i < 4; ++i) {
        int idx = tid + i * 128;
        int r = idx >> 3, c4 = (idx & 7) << 3;  // 64 rows x 64 cols via float4 pairs
        float4 v0 = *(const float4*)&qbase[(long)(t0 + r) * E3 + c4];
        float4 v1 = *(const float4*)&qbase[(long)(t0 + r) * E3 + c4 + 4];
        v0.x *= scale; v0.y *= scale; v0.z *= scale; v0.w *= scale;
        v1.x *= scale; v1.y *= scale; v1.z *= scale; v1.w *= scale;
        *(float4*)&Ks[r * AST + c4] = v0;
        *(float4*)&Ks[r * AST + c4 + 4] = v1;
    }
    __syncthreads();

    uint32_t q[8][4];
    {
        const uint32_t qa = ks_base + (uint32_t)((wq * 16 * AST + afrag_off) * 4);
#pragma unroll
        for (int ksx = 0; ksx < 8; ++ksx)
            LDMATRIX_X4(q[ksx][0], q[ksx][1], q[ksx][2], q[ksx][3], qa + ksx * 32);
    }

    float m0 = -CUDART_INF_F, m1 = -CUDART_INF_F, l0 = 0.f, l1 = 0.f;
    float o[8][4];
#pragma unroll
    for (int nt = 0; nt < 8; ++nt)
#pragma unroll
        for (int r = 0; r < 4; ++r) o[nt][r] = 0.f;

    for (int jt = 0; jt <= qt; ++jt) {
        const int k0 = jt * 64;
        __syncthreads();  // all warps done with Ks (q-frags / prior tile)

        // stage K [kpos][d] (float4 rows)
#pragma unroll
        for (int i = 0; i < 4; ++i) {
            int idx = tid + i * 128;
            int r = idx >> 3, c4 = (idx & 7) << 3;
            *(float4*)&Ks[r * AST + c4] =
                *(const float4*)&kbase[(long)(k0 + r) * E3 + c4];
            *(float4*)&Ks[r * AST + c4 + 4] =
                *(const float4*)&kbase[(long)(k0 + r) * E3 + c4 + 4];
        }
        // stage V transposed: Vt[d][kpos]; coalesced scalar LDG, conflict-free STS.128
#pragma unroll
        for (int i = 0; i < 8; ++i) {
            int idx = tid + i * 128;
            int kg = idx >> 6;        // kpos group 0..15
            int d  = idx & 63;
            const float* src = vbase + (long)(k0 + kg * 4) * E3 + d;
            float4 vv = make_float4(src[0], src[E3], src[2 * E3], src[3 * E3]);
            *(float4*)&Vt[d * AST + kg * 4] = vv;
        }
        __syncthreads();

        // ---- S = Q K^T (q regs + K ldmatrix)
        float sacc[8][4];
#pragma unroll
        for (int nt = 0; nt < 8; ++nt)
#pragma unroll
            for (int r = 0; r < 4; ++r) sacc[nt][r] = 0.f;

#pragma unroll
        for (int ksx = 0; ksx < 8; ++ksx) {
            const int kb = ksx * 8;
            uint32_t bfr[8][2];
#pragma unroll
            for (int p = 0; p < 4; ++p) {
                uint32_t addr = ks_base + (uint32_t)((bfrag_off + p * 16 * AST + kb) * 4);
                LDMATRIX_X4(bfr[2 * p][0], bfr[2 * p][1], bfr[2 * p + 1][0], bfr[2 * p + 1][1], addr);
            }
#pragma unroll
            for (int nt = 0; nt < 8; ++nt) MMA_TF32(sacc[nt], q[ksx], bfr[nt]);
        }

        // ---- causal mask (diagonal tile only)
        if (jt == qt) {
            int row0 = wq * 16 + lr, row1 = row0 + 8;
#pragma unroll
            for (int nt = 0; nt < 8; ++nt) {
                int col = nt * 8 + 2 * lc;
                if (col > row0)     sacc[nt][0] = -CUDART_INF_F;
                if (col + 1 > row0) sacc[nt][1] = -CUDART_INF_F;
                if (col > row1)     sacc[nt][2] = -CUDART_INF_F;
                if (col + 1 > row1) sacc[nt][3] = -CUDART_INF_F;
            }
        }

        // ---- online softmax
        float rm0 = -CUDART_INF_F, rm1 = -CUDART_INF_F;
#pragma unroll
        for (int nt = 0; nt < 8; ++nt) {
            rm0 = fmaxf(rm0, fmaxf(sacc[nt][0], sacc[nt][1]));
            rm1 = fmaxf(rm1, fmaxf(sacc[nt][2], sacc[nt][3]));
        }
        rm0 = fmaxf(rm0, __shfl_xor_sync(0xffffffffu, rm0, 1));
        rm0 = fmaxf(rm0, __shfl_xor_sync(0xffffffffu, rm0, 2));
        rm1 = fmaxf(rm1, __shfl_xor_sync(0xffffffffu, rm1, 1));
        rm1 = fmaxf(rm1, __shfl_xor_sync(0xffffffffu, rm1, 2));

        float mn0 = fmaxf(m0, rm0), mn1 = fmaxf(m1, rm1);
        float alpha0 = __expf(m0 - mn0), alpha1 = __expf(m1 - mn1);
        m0 = mn0; m1 = mn1;

        const int pr0 = wq * 16 + lr, pr1 = pr0 + 8;
        float rs0 = 0.f, rs1 = 0.f;
#pragma unroll
        for (int nt = 0; nt < 8; ++nt) {
            float p0 = __expf(sacc[nt][0] - mn0);
            float p1 = __expf(sacc[nt][1] - mn0);
            float p2 = __expf(sacc[nt][2] - mn1);
            float p3 = __expf(sacc[nt][3] - mn1);
            rs0 += p0 + p1; rs1 += p2 + p3;
            int cl = nt * 8 + 2 * lc;
            *(float2*)&Ps[pr0 * AST + cl] = make_float2(to_tf32(p0), to_tf32(p1));
            *(float2*)&Ps[pr1 * AST + cl] = make_float2(to_tf32(p2), to_tf32(p3));
        }
        rs0 += __shfl_xor_sync(0xffffffffu, rs0, 1);
        rs0 += __shfl_xor_sync(0xffffffffu, rs0, 2);
        rs1 += __shfl_xor_sync(0xffffffffu, rs1, 1);
        rs1 += __shfl_xor_sync(0xffffffffu, rs1, 2);
        l0 = l0 * alpha0 + rs0;
        l1 = l1 * alpha1 + rs1;
#pragma unroll
        for (int nt = 0; nt < 8; ++nt) {
            o[nt][0] *= alpha0; o[nt][1] *= alpha0;
            o[nt][2] *= alpha1; o[nt][3] *= alpha1;
        }
        __syncwarp();  // Ps rows warp-private: STS before ldmatrix

        // ---- O += P V (P + Vt ldmatrix)
#pragma unroll
        for (int ksx = 0; ksx < 8; ++ksx) {
            const int kb = ksx * 8;
            uint32_t a[4];
            {
                uint32_t addr = ps_base + (uint32_t)((wq * 16 * AST + afrag_off + kb) * 4);
                LDMATRIX_X4(a[0], a[1], a[2], a[3], addr);
            }
            uint32_t bfr[8][2];
#pragma unroll
            for (int p = 0; p < 4; ++p) {
                uint32_t addr = vt_base + (uint32_t)((bfrag_off + p * 16 * AST + kb) * 4);
                LDMATRIX_X4(bfr[2 * p][0], bfr[2 * p][1], bfr[2 * p + 1][0], bfr[2 * p + 1][1], addr);
            }
#pragma unroll
            for (int nt = 0; nt < 8; ++nt) MMA_TF32(o[nt], a, bfr[nt]);
        }
        __syncwarp();  // next Ps writes must not pass these reads
    }

    // ---- epilogue (rounded: feeds tf32 gemm2)
    float inv0 = 1.f / l0, inv1 = 1.f / l1;
    int r0 = t0 + wq * 16 + lr, r1 = r0 + 8;
#pragma unroll
    for (int nt = 0; nt < 8; ++nt) {
        int d = h * DHEAD + nt * 8 + 2 * lc;
        *(float2*)&out[((long)b * TT + r0) * TOTALE + d] =
            make_float2(to_tf32(o[nt][0] * inv0), to_tf32(o[nt][1] * inv0));
        *(float2*)&out[((long)b * TT + r1) * TOTALE + d] =
            make_float2(to_tf32(o[nt][2] * inv1), to_tf32(o[nt][3] * inv1));
    }
}

// ---------------------------------------------------------------------------
extern "C" void kernel_launch(void* const* d_in, const int* in_sizes, int n_in,
                              void* d_out, int out_size) {
    const float* x    = (const float*)d_in[0];
    const float* Wqkv = (const float*)d_in[1];
    const float* Wout = (const float*)d_in[2];
    float* out = (float*)d_out;

    void *qkv_p, *att_p, *xc_p, *wq_p, *wo_p;
    cudaGetSymbolAddress(&qkv_p, g_qkv);
    cudaGetSymbolAddress(&att_p, g_att);
    cudaGetSymbolAddress(&xc_p, g_xc);
    cudaGetSymbolAddress(&wq_p, g_wqkvc);
    cudaGetSymbolAddress(&wo_p, g_woutc);
    float* qkv = (float*)qkv_p;
    float* att = (float*)att_p;
    float* xc  = (float*)xc_p;
    float* wqc = (float*)wq_p;
    float* woc = (float*)wo_p;

    const int M = BB * TT;

    conv_tf32<<<(M * DMODEL / 4 + 255) / 256, 256>>>(x, xc, M * DMODEL / 4);
    conv_tf32<<<(E3 * DMODEL / 4 + 255) / 256, 256>>>(Wqkv, wqc, E3 * DMODEL / 4);
    conv_tf32<<<(DMODEL * TOTALE / 4 + 255) / 256, 256>>>(Wout, woc, DMODEL * TOTALE / 4);

    const int gsmem = 3 * GSTAGE * (int)sizeof(float);  // 110592 B
    cudaFuncSetAttribute(gemm_tf32<true>,  cudaFuncAttributeMaxDynamicSharedMemorySize, gsmem);
    cudaFuncSetAttribute(gemm_tf32<false>, cudaFuncAttributeMaxDynamicSharedMemorySize, gsmem);

    gemm_tf32<true><<<dim3(E3 / 128, M / 128), 256, gsmem>>>(xc, wqc, qkv, M, E3, DMODEL);

    const int asmem = 3 * 64 * AST * (int)sizeof(float);  // 52224 B
    cudaFuncSetAttribute(attn_tf32, cudaFuncAttributeMaxDynamicSharedMemorySize, asmem);
    attn_tf32<<<dim3(TT / 64, NHEADS, BB), 128, asmem>>>(qkv, att);

    gemm_tf32<false><<<dim3(DMODEL / 128, M / 128), 256, gsmem>>>(att, woc, out, M, DMODEL, DMODEL);
}